// round 11
// baseline (speedup 1.0000x reference)
#include <cuda_runtime.h>
#include <cuda_bf16.h>
#include <math.h>
#include <stdint.h>

// Problem constants
#define BATCH 32
#define DMODEL 384
#define NHEAD 8
#define HDIM 48
#define NS_TOK 1024
#define NT_TOK 256
#define NTOK 1280
#define KV_S 256
#define KV_T 64
#define KVTOK 320
#define FFDIM 1536
#define ATT_SCALE 0.14433756729740643f  // 1/sqrt(48)
#define EPS_LN 1e-5f
#define EPS_BN 1e-5f

// -------- scratch (device globals; no allocation allowed) --------
__device__ float g_xn[(size_t)BATCH * NTOK * DMODEL];
__device__ float g_cq[(size_t)BATCH * NTOK * DMODEL];
__device__ float g_ck[(size_t)BATCH * KVTOK * DMODEL];
__device__ float g_cv[(size_t)BATCH * KVTOK * DMODEL];
__device__ float g_q [(size_t)BATCH * NTOK * DMODEL];
__device__ float g_k [(size_t)BATCH * KVTOK * DMODEL];
__device__ float g_v [(size_t)BATCH * KVTOK * DMODEL];
__device__ float g_x1[(size_t)BATCH * NTOK * DMODEL];
__device__ float g_l2[(size_t)BATCH * NTOK * DMODEL];
__device__ float g_h [(size_t)BATCH * NTOK * FFDIM];
// tf32-pre-rounded weights
__device__ float g_wq[DMODEL * DMODEL];
__device__ float g_wk[DMODEL * DMODEL];
__device__ float g_wv[DMODEL * DMODEL];
__device__ float g_w1[FFDIM * DMODEL];
__device__ float g_w2[DMODEL * FFDIM];

// ---------------- helpers ----------------
__device__ __forceinline__ uint32_t f2tf32(float x) {
    uint32_t u;
    asm("cvt.rna.tf32.f32 %0, %1;" : "=r"(u) : "f"(x));
    return u;
}
__device__ __forceinline__ float f2tf32f(float x) { return __uint_as_float(f2tf32(x)); }
__device__ __forceinline__ uint32_t smem_u32(const void* p) {
    return (uint32_t)__cvta_generic_to_shared(p);
}
#define CP16(dst, src) asm volatile("cp.async.cg.shared.global [%0], [%1], 16;" :: "r"(dst), "l"(src))
#define CPCOMMIT() asm volatile("cp.async.commit_group;")
#define LDSM4(d0, d1, d2, d3, addr) \
    asm volatile("ldmatrix.sync.aligned.m8n8.x4.shared.b16 {%0,%1,%2,%3}, [%4];" \
                 : "=r"(d0), "=r"(d1), "=r"(d2), "=r"(d3) : "r"(addr))

__device__ __forceinline__ void mma_tf32(float* c, const uint32_t* a, uint32_t b0, uint32_t b1) {
    asm volatile(
        "mma.sync.aligned.m16n8k8.row.col.f32.tf32.tf32.f32 "
        "{%0,%1,%2,%3}, {%4,%5,%6,%7}, {%8,%9}, {%0,%1,%2,%3};\n"
        : "+f"(c[0]), "+f"(c[1]), "+f"(c[2]), "+f"(c[3])
        : "r"(a[0]), "r"(a[1]), "r"(a[2]), "r"(a[3]), "r"(b0), "r"(b1));
}

// ============== weight pre-round to tf32 (elementwise) =======================
__global__ void cvt_kernel(const float* __restrict__ src, float* __restrict__ dst, int n) {
    int i = blockIdx.x * 256 + threadIdx.x;
    if (i < n) dst[i] = f2tf32f(src[i]);
}

// ======================= LayerNorm (one block / token) =======================
template<bool ROUND>
__global__ void ln_kernel(const float* __restrict__ X, const float* __restrict__ gg,
                          const float* __restrict__ bb, float* __restrict__ Y) {
    int row = blockIdx.x, t = threadIdx.x;   // 128 threads
    const float* xp = X + (size_t)row * DMODEL;
    float v[3];
    float s = 0.f, ss = 0.f;
#pragma unroll
    for (int i = 0; i < 3; i++) { v[i] = xp[t + i * 128]; s += v[i]; ss += v[i] * v[i]; }
#pragma unroll
    for (int off = 16; off > 0; off >>= 1) {
        s  += __shfl_xor_sync(0xffffffffu, s,  off);
        ss += __shfl_xor_sync(0xffffffffu, ss, off);
    }
    __shared__ float sm[4], sm2[4];
    int wid = t >> 5;
    if ((t & 31) == 0) { sm[wid] = s; sm2[wid] = ss; }
    __syncthreads();
    s  = sm[0] + sm[1] + sm[2] + sm[3];
    ss = sm2[0] + sm2[1] + sm2[2] + sm2[3];
    float mean = s * (1.0f / DMODEL);
    float var  = ss * (1.0f / DMODEL) - mean * mean;
    float r = rsqrtf(var + EPS_LN);
    float* yp = Y + (size_t)row * DMODEL;
#pragma unroll
    for (int i = 0; i < 3; i++) {
        int c = t + i * 128;
        float o = (v[i] - mean) * r * gg[c] + bb[c];
        yp[c] = ROUND ? f2tf32f(o) : o;
    }
}

// ================= Depthwise 3x3 conv + BN, stride 1 (Q path) ================
__global__ void convq_kernel(const float* __restrict__ xn, const float* __restrict__ w,
                             const float* __restrict__ cb, const float* __restrict__ g,
                             const float* __restrict__ bb, float* __restrict__ out) {
    int b = blockIdx.y, tok = blockIdx.x, c = threadIdx.x;
    int Wd, base;
    if (tok < NS_TOK) { Wd = 32; base = 0; } else { Wd = 16; base = NS_TOK; }
    int loc = tok - base;
    int oy = loc / Wd, ox = loc % Wd;
    const float* wp = w + c * 9;
    float acc = 0.f;
#pragma unroll
    for (int ky = 0; ky < 3; ky++) {
        int iy = oy - 1 + ky;
        if (iy < 0 || iy >= Wd) continue;
#pragma unroll
        for (int kx = 0; kx < 3; kx++) {
            int ix = ox - 1 + kx;
            if (ix < 0 || ix >= Wd) continue;
            acc += wp[ky * 3 + kx] * xn[((size_t)b * NTOK + base + iy * Wd + ix) * DMODEL + c];
        }
    }
    float sc = g[c] * rsqrtf(1.0f + EPS_BN);
    out[((size_t)b * NTOK + tok) * DMODEL + c] = f2tf32f((acc + cb[c]) * sc + bb[c]);
}

// ============ Depthwise 3x3 conv + BN, stride 2, fused K & V =================
__global__ void convkv_kernel(const float* __restrict__ xn,
                              const float* __restrict__ wk, const float* __restrict__ cbk,
                              const float* __restrict__ gk, const float* __restrict__ bbk,
                              const float* __restrict__ wv, const float* __restrict__ cbv,
                              const float* __restrict__ gv, const float* __restrict__ bbv,
                              float* __restrict__ outk, float* __restrict__ outv) {
    int b = blockIdx.y, tok = blockIdx.x, c = threadIdx.x;
    int Wd, inW, inBase, base;
    if (tok < KV_S) { Wd = 16; inW = 32; inBase = 0; base = 0; }
    else            { Wd = 8;  inW = 16; inBase = NS_TOK; base = KV_S; }
    int loc = tok - base;
    int oy = loc / Wd, ox = loc % Wd;
    const float* wpk = wk + c * 9;
    const float* wpv = wv + c * 9;
    float acck = 0.f, accv = 0.f;
#pragma unroll
    for (int ky = 0; ky < 3; ky++) {
        int iy = 2 * oy - 1 + ky;
        if (iy < 0 || iy >= inW) continue;
#pragma unroll
        for (int kx = 0; kx < 3; kx++) {
            int ix = 2 * ox - 1 + kx;
            if (ix < 0 || ix >= inW) continue;
            float xv = xn[((size_t)b * NTOK + inBase + iy * inW + ix) * DMODEL + c];
            acck += wpk[ky * 3 + kx] * xv;
            accv += wpv[ky * 3 + kx] * xv;
        }
    }
    size_t oidx = ((size_t)b * KVTOK + tok) * DMODEL + c;
    outk[oidx] = f2tf32f((acck + cbk[c]) * (gk[c] * rsqrtf(1.0f + EPS_BN)) + bbk[c]);
    outv[oidx] = f2tf32f((accv + cbv[c]) * (gv[c] * rsqrtf(1.0f + EPS_BN)) + bbv[c]);
}

// ========== TF32 tensor-core GEMM, 4-stage cp.async + ldmatrix ===============
// C = A @ W^T + bias. A[M,K], W[N,K] row-major, both PRE-ROUNDED to tf32 bits.
// 128x128 tile, BK=16, 4 stages, 8 warps (2x4), warp tile 64x32.
#define BM 128
#define BN 128
#define BK2 16
#define GSTR 20            // floats per smem row (16 + 4 pad)
#define STAGES 4
#define STAGE_BYTES (128 * GSTR * 4)   // one stage of one matrix: 10240 B
#define GEMM_SMEM (STAGES * STAGE_BYTES * 2)

template<int EPI>
__global__ void __launch_bounds__(256) gemm_tc(
        const float* __restrict__ A, const float* __restrict__ W,
        const float* __restrict__ bias, const float* __restrict__ resid,
        float* __restrict__ C, int M, int Nn, int Kk) {
    extern __shared__ __align__(16) char smraw[];
    float (*As)[BM][GSTR] = (float(*)[BM][GSTR])smraw;
    float (*Ws)[BN][GSTR] = (float(*)[BN][GSTR])(smraw + STAGES * STAGE_BYTES);

    int t = threadIdx.x;
    int lane = t & 31, wid = t >> 5;
    int wm = (wid & 1) * 64;
    int wn = (wid >> 1) * 32;
    int bm = blockIdx.y * BM, bn = blockIdx.x * BN;
    int lr = lane >> 2, lc = lane & 3;

    float acc[4][4][4];
#pragma unroll
    for (int mi = 0; mi < 4; mi++)
#pragma unroll
        for (int ni = 0; ni < 4; ni++)
#pragma unroll
            for (int f = 0; f < 4; f++) acc[mi][ni][f] = 0.f;

    // cp.async coords: 2 float4 per matrix per stage per thread
    int r0 = t >> 2, c4 = (t & 3) * 4;          // rows 0..63
    int r1 = r0 + 64;                            // rows 64..127

    // ldmatrix per-lane base addresses
    int arow = wm + (lane & 7) + ((lane >> 3) & 1) * 8;
    int acol = ((lane >> 4) & 1) * 4;
    uint32_t aAddr = smem_u32(&As[0][arow][acol]);
    int brow = wn + (lane & 7) + ((lane >> 4) & 1) * 8;
    int bcol = ((lane >> 3) & 1) * 4;
    uint32_t wAddr = smem_u32(&Ws[0][brow][bcol]);

    int niter = Kk / BK2;
    // prologue: stages 0..2
#pragma unroll
    for (int p = 0; p < STAGES - 1; p++) {
        int k0 = p * BK2;
        CP16(smem_u32(&As[p][r0][c4]), &A[(size_t)(bm + r0) * Kk + k0 + c4]);
        CP16(smem_u32(&As[p][r1][c4]), &A[(size_t)(bm + r1) * Kk + k0 + c4]);
        CP16(smem_u32(&Ws[p][r0][c4]), &W[(size_t)(bn + r0) * Kk + k0 + c4]);
        CP16(smem_u32(&Ws[p][r1][c4]), &W[(size_t)(bn + r1) * Kk + k0 + c4]);
        CPCOMMIT();
    }

    for (int it = 0; it < niter; it++) {
        int st = it & (STAGES - 1);
        if (it + STAGES - 1 < niter) {
            int ns = (it + STAGES - 1) & (STAGES - 1);
            int k0 = (it + STAGES - 1) * BK2;
            CP16(smem_u32(&As[ns][r0][c4]), &A[(size_t)(bm + r0) * Kk + k0 + c4]);
            CP16(smem_u32(&As[ns][r1][c4]), &A[(size_t)(bm + r1) * Kk + k0 + c4]);
            CP16(smem_u32(&Ws[ns][r0][c4]), &W[(size_t)(bn + r0) * Kk + k0 + c4]);
            CP16(smem_u32(&Ws[ns][r1][c4]), &W[(size_t)(bn + r1) * Kk + k0 + c4]);
            CPCOMMIT();
            asm volatile("cp.async.wait_group %0;" :: "n"(STAGES - 1));
        } else if (it + 2 < niter) {
            asm volatile("cp.async.wait_group 2;");
        } else if (it + 1 < niter) {
            asm volatile("cp.async.wait_group 1;");
        } else {
            asm volatile("cp.async.wait_group 0;");
        }
        __syncthreads();

        uint32_t stA = aAddr + st * STAGE_BYTES;
        uint32_t stW = wAddr + st * STAGE_BYTES;
#pragma unroll
        for (int ks = 0; ks < BK2; ks += 8) {
            uint32_t af[4][4], bf[4][2];
#pragma unroll
            for (int mi = 0; mi < 4; mi++)
                LDSM4(af[mi][0], af[mi][1], af[mi][2], af[mi][3],
                      stA + (mi * 16 * GSTR + ks) * 4);
            LDSM4(bf[0][0], bf[0][1], bf[1][0], bf[1][1], stW + ks * 4);
            LDSM4(bf[2][0], bf[2][1], bf[3][0], bf[3][1], stW + (16 * GSTR + ks) * 4);
#pragma unroll
            for (int mi = 0; mi < 4; mi++)
#pragma unroll
                for (int ni = 0; ni < 4; ni++)
                    mma_tf32(acc[mi][ni], af[mi], bf[ni][0], bf[ni][1]);
        }
        __syncthreads();
    }

    // epilogue
#pragma unroll
    for (int mi = 0; mi < 4; mi++) {
#pragma unroll
        for (int ni = 0; ni < 4; ni++) {
            int rr0 = bm + wm + mi * 16 + lr;
            int cc = bn + wn + ni * 8 + 2 * lc;
            float b0 = bias[cc], b1 = bias[cc + 1];
#pragma unroll
            for (int half = 0; half < 2; half++) {
                int r = rr0 + half * 8;
                float v0 = acc[mi][ni][half * 2 + 0] + b0;
                float v1 = acc[mi][ni][half * 2 + 1] + b1;
                if (EPI == 1) {
                    v0 = f2tf32f(0.5f * v0 * (1.0f + erff(v0 * 0.70710678118654752f)));
                    v1 = f2tf32f(0.5f * v1 * (1.0f + erff(v1 * 0.70710678118654752f)));
                } else if (EPI == 2) {
                    const float2 rv = *(const float2*)&resid[(size_t)r * Nn + cc];
                    v0 += rv.x; v1 += rv.y;
                }
                float2 ov = {v0, v1};
                *(float2*)&C[(size_t)r * Nn + cc] = ov;
            }
        }
    }
}

// ==================== TF32 tensor-core flash attention =======================
// Block: 128 threads (4 warps). Each warp owns 16 queries; block owns 64 and
// shares K/V smem tiles of 32 kv. Online softmax with register fragments.
__global__ void __launch_bounds__(128) attn_mma(
        const float* __restrict__ Q, const float* __restrict__ K,
        const float* __restrict__ V, const float* __restrict__ X,
        float* __restrict__ O, int q_off, int kv_off, int kv_len) {
    int b = blockIdx.z, h = blockIdx.y;
    int t = threadIdx.x;
    int w = t >> 5, lane = t & 31;
    int lr = lane >> 2, lc = lane & 3;
    int qbase = q_off + blockIdx.x * 64 + w * 16;

    __shared__ __align__(16) uint32_t ks_sm[32][52];
    __shared__ __align__(16) uint32_t vt_sm[HDIM][36];
    __shared__ __align__(16) float ps_sm[4][16][36];

    // Q fragments, scale folded in; resident across kv loop
    uint32_t aq[6][4];
#pragma unroll
    for (int kd = 0; kd < 6; kd++) {
        const float* qp0 = &Q[((size_t)(b * NTOK + qbase + lr)) * DMODEL + h * HDIM + kd * 8 + lc];
        const float* qp1 = qp0 + 8 * DMODEL;
        aq[kd][0] = f2tf32(qp0[0] * ATT_SCALE);
        aq[kd][1] = f2tf32(qp1[0] * ATT_SCALE);
        aq[kd][2] = f2tf32(qp0[4] * ATT_SCALE);
        aq[kd][3] = f2tf32(qp1[4] * ATT_SCALE);
    }

    float oacc[6][4];
#pragma unroll
    for (int ni = 0; ni < 6; ni++)
#pragma unroll
        for (int f = 0; f < 4; f++) oacc[ni][f] = 0.f;
    float m0 = -1e30f, m1 = -1e30f, l0 = 0.f, l1 = 0.f;

    for (int kt = 0; kt < kv_len; kt += 32) {
        // load K tile (row-major tf32) and V tile transposed
#pragma unroll
        for (int i = 0; i < 3; i++) {
            int e = t + i * 128;
            int r = e / 12, cc4 = (e % 12) * 4;
            size_t g = ((size_t)(b * KVTOK + kv_off + kt + r)) * DMODEL + h * HDIM + cc4;
            float4 kv4 = *(const float4*)&K[g];
            uint4 ku = {f2tf32(kv4.x), f2tf32(kv4.y), f2tf32(kv4.z), f2tf32(kv4.w)};
            *(uint4*)&ks_sm[r][cc4] = ku;
            float4 vv4 = *(const float4*)&V[g];
            vt_sm[cc4 + 0][r] = f2tf32(vv4.x);
            vt_sm[cc4 + 1][r] = f2tf32(vv4.y);
            vt_sm[cc4 + 2][r] = f2tf32(vv4.z);
            vt_sm[cc4 + 3][r] = f2tf32(vv4.w);
        }
        __syncthreads();

        // S = Q @ K^T  (16 x 32)
        float sacc[4][4];
#pragma unroll
        for (int ni = 0; ni < 4; ni++)
#pragma unroll
            for (int f = 0; f < 4; f++) sacc[ni][f] = 0.f;
#pragma unroll
        for (int kd = 0; kd < 6; kd++) {
#pragma unroll
            for (int ni = 0; ni < 4; ni++) {
                uint32_t b0 = ks_sm[ni * 8 + lr][kd * 8 + lc];
                uint32_t b1 = ks_sm[ni * 8 + lr][kd * 8 + lc + 4];
                mma_tf32(sacc[ni], aq[kd], b0, b1);
            }
        }

        // online softmax on fragments (rows lr and lr+8)
        float mt0 = -1e30f, mt1 = -1e30f;
#pragma unroll
        for (int ni = 0; ni < 4; ni++) {
            mt0 = fmaxf(mt0, fmaxf(sacc[ni][0], sacc[ni][1]));
            mt1 = fmaxf(mt1, fmaxf(sacc[ni][2], sacc[ni][3]));
        }
        mt0 = fmaxf(mt0, __shfl_xor_sync(0xffffffffu, mt0, 1));
        mt0 = fmaxf(mt0, __shfl_xor_sync(0xffffffffu, mt0, 2));
        mt1 = fmaxf(mt1, __shfl_xor_sync(0xffffffffu, mt1, 1));
        mt1 = fmaxf(mt1, __shfl_xor_sync(0xffffffffu, mt1, 2));
        float mn0 = fmaxf(m0, mt0), mn1 = fmaxf(m1, mt1);
        float cr0 = __expf(m0 - mn0), cr1 = __expf(m1 - mn1);
        float ps0 = 0.f, ps1 = 0.f;
#pragma unroll
        for (int ni = 0; ni < 4; ni++) {
            float p00 = __expf(sacc[ni][0] - mn0);
            float p01 = __expf(sacc[ni][1] - mn0);
            float p10 = __expf(sacc[ni][2] - mn1);
            float p11 = __expf(sacc[ni][3] - mn1);
            ps0 += p00 + p01; ps1 += p10 + p11;
            float2 w0 = {p00, p01};
            float2 w1 = {p10, p11};
            *(float2*)&ps_sm[w][lr][ni * 8 + 2 * lc] = w0;
            *(float2*)&ps_sm[w][lr + 8][ni * 8 + 2 * lc] = w1;
        }
        ps0 += __shfl_xor_sync(0xffffffffu, ps0, 1);
        ps0 += __shfl_xor_sync(0xffffffffu, ps0, 2);
        ps1 += __shfl_xor_sync(0xffffffffu, ps1, 1);
        ps1 += __shfl_xor_sync(0xffffffffu, ps1, 2);
        l0 = l0 * cr0 + ps0;
        l1 = l1 * cr1 + ps1;
        m0 = mn0; m1 = mn1;
#pragma unroll
        for (int ni = 0; ni < 6; ni++) {
            oacc[ni][0] *= cr0; oacc[ni][1] *= cr0;
            oacc[ni][2] *= cr1; oacc[ni][3] *= cr1;
        }
        __syncwarp();

        // O += P @ V   (16 x 48, k = 32)
#pragma unroll
        for (int kd = 0; kd < 4; kd++) {
            uint32_t ap[4];
            ap[0] = f2tf32(ps_sm[w][lr][kd * 8 + lc]);
            ap[1] = f2tf32(ps_sm[w][lr + 8][kd * 8 + lc]);
            ap[2] = f2tf32(ps_sm[w][lr][kd * 8 + lc + 4]);
            ap[3] = f2tf32(ps_sm[w][lr + 8][kd * 8 + lc + 4]);
#pragma unroll
            for (int ni = 0; ni < 6; ni++) {
                uint32_t b0 = vt_sm[ni * 8 + lr][kd * 8 + lc];
                uint32_t b1 = vt_sm[ni * 8 + lr][kd * 8 + lc + 4];
                mma_tf32(oacc[ni], ap, b0, b1);
            }
        }
        __syncthreads();
    }

    float rc0 = 1.0f / l0, rc1 = 1.0f / l1;
#pragma unroll
    for (int ni = 0; ni < 6; ni++) {
        int col = h * HDIM + ni * 8 + 2 * lc;
        size_t g0 = ((size_t)(b * NTOK + qbase + lr)) * DMODEL + col;
        size_t g1 = g0 + (size_t)8 * DMODEL;
        float2 x0 = *(const float2*)&X[g0];
        float2 x1 = *(const float2*)&X[g1];
        float2 o0 = {x0.x + oacc[ni][0] * rc0, x0.y + oacc[ni][1] * rc0};
        float2 o1 = {x1.x + oacc[ni][2] * rc1, x1.y + oacc[ni][3] * rc1};
        *(float2*)&O[g0] = o0;
        *(float2*)&O[g1] = o1;
    }
}

// ================================ launch =====================================
extern "C" void kernel_launch(void* const* d_in, const int* in_sizes, int n_in,
                              void* d_out, int out_size) {
    const float* x     = (const float*)d_in[0];
    const float* ln1_g = (const float*)d_in[1];
    const float* ln1_b = (const float*)d_in[2];
    const float* dwq_w = (const float*)d_in[3];
    const float* dwq_b = (const float*)d_in[4];
    const float* bnq_g = (const float*)d_in[5];
    const float* bnq_b = (const float*)d_in[6];
    const float* dwk_w = (const float*)d_in[7];
    const float* dwk_b = (const float*)d_in[8];
    const float* bnk_g = (const float*)d_in[9];
    const float* bnk_b = (const float*)d_in[10];
    const float* dwv_w = (const float*)d_in[11];
    const float* dwv_b = (const float*)d_in[12];
    const float* bnv_g = (const float*)d_in[13];
    const float* bnv_b = (const float*)d_in[14];
    const float* pq_w  = (const float*)d_in[15];
    const float* pq_b  = (const float*)d_in[16];
    const float* pk_w  = (const float*)d_in[17];
    const float* pk_b  = (const float*)d_in[18];
    const float* pv_w  = (const float*)d_in[19];
    const float* pv_b  = (const float*)d_in[20];
    const float* ln2_g = (const float*)d_in[21];
    const float* ln2_b = (const float*)d_in[22];
    const float* ff1_w = (const float*)d_in[23];
    const float* ff1_b = (const float*)d_in[24];
    const float* ff2_w = (const float*)d_in[25];
    const float* ff2_b = (const float*)d_in[26];
    float* out = (float*)d_out;

    float *xn, *cq, *ck, *cv, *q, *k, *v, *x1, *l2, *hbuf;
    float *wq, *wk, *wv, *w1, *w2;
    cudaGetSymbolAddress((void**)&xn,   g_xn);
    cudaGetSymbolAddress((void**)&cq,   g_cq);
    cudaGetSymbolAddress((void**)&ck,   g_ck);
    cudaGetSymbolAddress((void**)&cv,   g_cv);
    cudaGetSymbolAddress((void**)&q,    g_q);
    cudaGetSymbolAddress((void**)&k,    g_k);
    cudaGetSymbolAddress((void**)&v,    g_v);
    cudaGetSymbolAddress((void**)&x1,   g_x1);
    cudaGetSymbolAddress((void**)&l2,   g_l2);
    cudaGetSymbolAddress((void**)&hbuf, g_h);
    cudaGetSymbolAddress((void**)&wq,   g_wq);
    cudaGetSymbolAddress((void**)&wk,   g_wk);
    cudaGetSymbolAddress((void**)&wv,   g_wv);
    cudaGetSymbolAddress((void**)&w1,   g_w1);
    cudaGetSymbolAddress((void**)&w2,   g_w2);

    cudaFuncSetAttribute(gemm_tc<0>, cudaFuncAttributeMaxDynamicSharedMemorySize, GEMM_SMEM);
    cudaFuncSetAttribute(gemm_tc<1>, cudaFuncAttributeMaxDynamicSharedMemorySize, GEMM_SMEM);
    cudaFuncSetAttribute(gemm_tc<2>, cudaFuncAttributeMaxDynamicSharedMemorySize, GEMM_SMEM);

    const int Mq = BATCH * NTOK;    // 40960
    const int Mkv = BATCH * KVTOK;  // 10240
    const int NDD = DMODEL * DMODEL;
    const int NFD = FFDIM * DMODEL;

    // weight pre-round (small; runs every call for determinism)
    cvt_kernel<<<(NDD + 255) / 256, 256>>>(pq_w, wq, NDD);
    cvt_kernel<<<(NDD + 255) / 256, 256>>>(pk_w, wk, NDD);
    cvt_kernel<<<(NDD + 255) / 256, 256>>>(pv_w, wv, NDD);
    cvt_kernel<<<(NFD + 255) / 256, 256>>>(ff1_w, w1, NFD);
    cvt_kernel<<<(NFD + 255) / 256, 256>>>(ff2_w, w2, NFD);

    ln_kernel<false><<<Mq, 128>>>(x, ln1_g, ln1_b, xn);
    convq_kernel<<<dim3(NTOK, BATCH), DMODEL>>>(xn, dwq_w, dwq_b, bnq_g, bnq_b, cq);
    convkv_kernel<<<dim3(KVTOK, BATCH), DMODEL>>>(xn, dwk_w, dwk_b, bnk_g, bnk_b,
                                                  dwv_w, dwv_b, bnv_g, bnv_b, ck, cv);
    gemm_tc<0><<<dim3(DMODEL / BN, Mq / BM), 256, GEMM_SMEM>>>(cq, wq, pq_b, nullptr, q, Mq, DMODEL, DMODEL);
    gemm_tc<0><<<dim3(DMODEL / BN, Mkv / BM), 256, GEMM_SMEM>>>(ck, wk, pk_b, nullptr, k, Mkv, DMODEL, DMODEL);
    gemm_tc<0><<<dim3(DMODEL / BN, Mkv / BM), 256, GEMM_SMEM>>>(cv, wv, pv_b, nullptr, v, Mkv, DMODEL, DMODEL);
    attn_mma<<<dim3(NS_TOK / 64, NHEAD, BATCH), 128>>>(q, k, v, x, x1, 0, 0, KVTOK);
    attn_mma<<<dim3(NT_TOK / 64, NHEAD, BATCH), 128>>>(q, k, v, x, x1, NS_TOK, KV_S, KV_T);
    ln_kernel<true><<<Mq, 128>>>(x1, ln2_g, ln2_b, l2);
    gemm_tc<1><<<dim3(FFDIM / BN, Mq / BM), 256, GEMM_SMEM>>>(l2, w1, ff1_b, nullptr, hbuf, Mq, FFDIM, DMODEL);
    gemm_tc<2><<<dim3(DMODEL / BN, Mq / BM), 256, GEMM_SMEM>>>(hbuf, w2, ff2_b, x1, out, Mq, DMODEL, FFDIM);
}

// round 12
// speedup vs baseline: 1.3605x; 1.3605x over previous
#include <cuda_runtime.h>
#include <cuda_bf16.h>
#include <math.h>
#include <stdint.h>

// Problem constants
#define BATCH 32
#define DMODEL 384
#define NHEAD 8
#define HDIM 48
#define NS_TOK 1024
#define NT_TOK 256
#define NTOK 1280
#define KV_S 256
#define KV_T 64
#define KVTOK 320
#define FFDIM 1536
#define ATT_SCALE 0.14433756729740643f  // 1/sqrt(48)
#define EPS_LN 1e-5f
#define EPS_BN 1e-5f

// -------- scratch (device globals; no allocation allowed) --------
__device__ float g_xn[(size_t)BATCH * NTOK * DMODEL];
__device__ __nv_bfloat16 g_cq[(size_t)BATCH * NTOK * DMODEL];
__device__ __nv_bfloat16 g_ck[(size_t)BATCH * KVTOK * DMODEL];
__device__ __nv_bfloat16 g_cv[(size_t)BATCH * KVTOK * DMODEL];
__device__ float g_q [(size_t)BATCH * NTOK * DMODEL];
__device__ float g_k [(size_t)BATCH * KVTOK * DMODEL];
__device__ float g_v [(size_t)BATCH * KVTOK * DMODEL];
__device__ float g_x1[(size_t)BATCH * NTOK * DMODEL];
__device__ __nv_bfloat16 g_l2[(size_t)BATCH * NTOK * DMODEL];
__device__ __nv_bfloat16 g_h [(size_t)BATCH * NTOK * FFDIM];
// bf16-pre-rounded weights
__device__ __nv_bfloat16 g_wq[DMODEL * DMODEL];
__device__ __nv_bfloat16 g_wk[DMODEL * DMODEL];
__device__ __nv_bfloat16 g_wv[DMODEL * DMODEL];
__device__ __nv_bfloat16 g_w1[FFDIM * DMODEL];
__device__ __nv_bfloat16 g_w2[DMODEL * FFDIM];

// ---------------- helpers ----------------
__device__ __forceinline__ uint32_t f2tf32(float x) {
    uint32_t u;
    asm("cvt.rna.tf32.f32 %0, %1;" : "=r"(u) : "f"(x));
    return u;
}
__device__ __forceinline__ uint32_t smem_u32(const void* p) {
    return (uint32_t)__cvta_generic_to_shared(p);
}
#define CP16(dst, src) asm volatile("cp.async.cg.shared.global [%0], [%1], 16;" :: "r"(dst), "l"(src))
#define CPCOMMIT() asm volatile("cp.async.commit_group;")
#define LDSM4(d0, d1, d2, d3, addr) \
    asm volatile("ldmatrix.sync.aligned.m8n8.x4.shared.b16 {%0,%1,%2,%3}, [%4];" \
                 : "=r"(d0), "=r"(d1), "=r"(d2), "=r"(d3) : "r"(addr))

__device__ __forceinline__ void mma_tf32(float* c, const uint32_t* a, uint32_t b0, uint32_t b1) {
    asm volatile(
        "mma.sync.aligned.m16n8k8.row.col.f32.tf32.tf32.f32 "
        "{%0,%1,%2,%3}, {%4,%5,%6,%7}, {%8,%9}, {%0,%1,%2,%3};\n"
        : "+f"(c[0]), "+f"(c[1]), "+f"(c[2]), "+f"(c[3])
        : "r"(a[0]), "r"(a[1]), "r"(a[2]), "r"(a[3]), "r"(b0), "r"(b1));
}
__device__ __forceinline__ void mma_bf16(float* c, const uint32_t* a, uint32_t b0, uint32_t b1) {
    asm volatile(
        "mma.sync.aligned.m16n8k16.row.col.f32.bf16.bf16.f32 "
        "{%0,%1,%2,%3}, {%4,%5,%6,%7}, {%8,%9}, {%0,%1,%2,%3};\n"
        : "+f"(c[0]), "+f"(c[1]), "+f"(c[2]), "+f"(c[3])
        : "r"(a[0]), "r"(a[1]), "r"(a[2]), "r"(a[3]), "r"(b0), "r"(b1));
}

// ============== weight pre-round to bf16 (elementwise) =======================
__global__ void cvt_kernel(const float* __restrict__ src, __nv_bfloat16* __restrict__ dst, int n) {
    int i = blockIdx.x * 256 + threadIdx.x;
    if (i < n) dst[i] = __float2bfloat16(src[i]);
}

// ======================= LayerNorm (one block / token) =======================
template<typename OUT>
__global__ void ln_kernel(const float* __restrict__ X, const float* __restrict__ gg,
                          const float* __restrict__ bb, OUT* __restrict__ Y) {
    int row = blockIdx.x, t = threadIdx.x;   // 128 threads
    const float* xp = X + (size_t)row * DMODEL;
    float v[3];
    float s = 0.f, ss = 0.f;
#pragma unroll
    for (int i = 0; i < 3; i++) { v[i] = xp[t + i * 128]; s += v[i]; ss += v[i] * v[i]; }
#pragma unroll
    for (int off = 16; off > 0; off >>= 1) {
        s  += __shfl_xor_sync(0xffffffffu, s,  off);
        ss += __shfl_xor_sync(0xffffffffu, ss, off);
    }
    __shared__ float sm[4], sm2[4];
    int wid = t >> 5;
    if ((t & 31) == 0) { sm[wid] = s; sm2[wid] = ss; }
    __syncthreads();
    s  = sm[0] + sm[1] + sm[2] + sm[3];
    ss = sm2[0] + sm2[1] + sm2[2] + sm2[3];
    float mean = s * (1.0f / DMODEL);
    float var  = ss * (1.0f / DMODEL) - mean * mean;
    float r = rsqrtf(var + EPS_LN);
    OUT* yp = Y + (size_t)row * DMODEL;
#pragma unroll
    for (int i = 0; i < 3; i++) {
        int c = t + i * 128;
        yp[c] = (OUT)((v[i] - mean) * r * gg[c] + bb[c]);
    }
}

// ================= Depthwise 3x3 conv + BN, stride 1 (Q path) ================
__global__ void convq_kernel(const float* __restrict__ xn, const float* __restrict__ w,
                             const float* __restrict__ cb, const float* __restrict__ g,
                             const float* __restrict__ bb, __nv_bfloat16* __restrict__ out) {
    int b = blockIdx.y, tok = blockIdx.x, c = threadIdx.x;
    int Wd, base;
    if (tok < NS_TOK) { Wd = 32; base = 0; } else { Wd = 16; base = NS_TOK; }
    int loc = tok - base;
    int oy = loc / Wd, ox = loc % Wd;
    const float* wp = w + c * 9;
    float acc = 0.f;
#pragma unroll
    for (int ky = 0; ky < 3; ky++) {
        int iy = oy - 1 + ky;
        if (iy < 0 || iy >= Wd) continue;
#pragma unroll
        for (int kx = 0; kx < 3; kx++) {
            int ix = ox - 1 + kx;
            if (ix < 0 || ix >= Wd) continue;
            acc += wp[ky * 3 + kx] * xn[((size_t)b * NTOK + base + iy * Wd + ix) * DMODEL + c];
        }
    }
    float sc = g[c] * rsqrtf(1.0f + EPS_BN);
    out[((size_t)b * NTOK + tok) * DMODEL + c] = __float2bfloat16((acc + cb[c]) * sc + bb[c]);
}

// ============ Depthwise 3x3 conv + BN, stride 2, fused K & V =================
__global__ void convkv_kernel(const float* __restrict__ xn,
                              const float* __restrict__ wk, const float* __restrict__ cbk,
                              const float* __restrict__ gk, const float* __restrict__ bbk,
                              const float* __restrict__ wv, const float* __restrict__ cbv,
                              const float* __restrict__ gv, const float* __restrict__ bbv,
                              __nv_bfloat16* __restrict__ outk, __nv_bfloat16* __restrict__ outv) {
    int b = blockIdx.y, tok = blockIdx.x, c = threadIdx.x;
    int Wd, inW, inBase, base;
    if (tok < KV_S) { Wd = 16; inW = 32; inBase = 0; base = 0; }
    else            { Wd = 8;  inW = 16; inBase = NS_TOK; base = KV_S; }
    int loc = tok - base;
    int oy = loc / Wd, ox = loc % Wd;
    const float* wpk = wk + c * 9;
    const float* wpv = wv + c * 9;
    float acck = 0.f, accv = 0.f;
#pragma unroll
    for (int ky = 0; ky < 3; ky++) {
        int iy = 2 * oy - 1 + ky;
        if (iy < 0 || iy >= inW) continue;
#pragma unroll
        for (int kx = 0; kx < 3; kx++) {
            int ix = 2 * ox - 1 + kx;
            if (ix < 0 || ix >= inW) continue;
            float xv = xn[((size_t)b * NTOK + inBase + iy * inW + ix) * DMODEL + c];
            acck += wpk[ky * 3 + kx] * xv;
            accv += wpv[ky * 3 + kx] * xv;
        }
    }
    size_t oidx = ((size_t)b * KVTOK + tok) * DMODEL + c;
    outk[oidx] = __float2bfloat16((acck + cbk[c]) * (gk[c] * rsqrtf(1.0f + EPS_BN)) + bbk[c]);
    outv[oidx] = __float2bfloat16((accv + cbv[c]) * (gv[c] * rsqrtf(1.0f + EPS_BN)) + bbv[c]);
}

// ========== BF16 tensor-core GEMM, 4-stage cp.async + ldmatrix ===============
// C = A @ W^T + bias. A[M,K], W[N,K] row-major bf16. 128x128 tile, BK=32,
// 4 stages, 8 warps (2x4), warp tile 64x32, mma m16n8k16.
// EPI: 0 -> fp32 out; 1 -> gelu, bf16 out; 2 -> +resid(fp32), fp32 out.
#define BM 128
#define BN 128
#define BK2 32
#define GSTR 40            // bf16 per smem row (32 + 8 pad) = 80 bytes
#define STAGES 4
#define STAGE_BYTES (128 * GSTR * 2)   // 10240 B
#define GEMM_SMEM (STAGES * STAGE_BYTES * 2)

template<int EPI>
__global__ void __launch_bounds__(256) gemm_tc(
        const __nv_bfloat16* __restrict__ A, const __nv_bfloat16* __restrict__ W,
        const float* __restrict__ bias, const float* __restrict__ resid,
        void* __restrict__ Cv, int M, int Nn, int Kk) {
    extern __shared__ __align__(16) char smraw[];
    __nv_bfloat16 (*As)[BM][GSTR] = (__nv_bfloat16(*)[BM][GSTR])smraw;
    __nv_bfloat16 (*Ws)[BN][GSTR] = (__nv_bfloat16(*)[BN][GSTR])(smraw + STAGES * STAGE_BYTES);

    int t = threadIdx.x;
    int lane = t & 31, wid = t >> 5;
    int wm = (wid & 1) * 64;
    int wn = (wid >> 1) * 32;
    int bm = blockIdx.y * BM, bn = blockIdx.x * BN;
    int lr = lane >> 2, lc = lane & 3;

    float acc[4][4][4];
#pragma unroll
    for (int mi = 0; mi < 4; mi++)
#pragma unroll
        for (int ni = 0; ni < 4; ni++)
#pragma unroll
            for (int f = 0; f < 4; f++) acc[mi][ni][f] = 0.f;

    // cp.async coords: row = t>>2 (+64), 16B chunk = (t&3)*8 bf16
    int r0 = t >> 2, c8 = (t & 3) * 8;
    int r1 = r0 + 64;

    // ldmatrix per-lane base addresses (identical formula for A and B):
    // lanes 0-7: rows +0 k-lo | 8-15: rows +8 k-lo | 16-23: rows +0 k-hi | 24-31: rows +8 k-hi
    int arow = wm + (lane & 7) + ((lane >> 3) & 1) * 8;
    int acol = ((lane >> 4) & 1) * 8;   // bf16 units (16 bytes)
    uint32_t aAddr = smem_u32(&As[0][arow][acol]);
    int brow = wn + (lane & 7) + ((lane >> 3) & 1) * 8;
    int bcol = ((lane >> 4) & 1) * 8;
    uint32_t wAddr = smem_u32(&Ws[0][brow][bcol]);

    int niter = Kk / BK2;
    // prologue: stages 0..2
#pragma unroll
    for (int p = 0; p < STAGES - 1; p++) {
        int k0 = p * BK2;
        CP16(smem_u32(&As[p][r0][c8]), &A[(size_t)(bm + r0) * Kk + k0 + c8]);
        CP16(smem_u32(&As[p][r1][c8]), &A[(size_t)(bm + r1) * Kk + k0 + c8]);
        CP16(smem_u32(&Ws[p][r0][c8]), &W[(size_t)(bn + r0) * Kk + k0 + c8]);
        CP16(smem_u32(&Ws[p][r1][c8]), &W[(size_t)(bn + r1) * Kk + k0 + c8]);
        CPCOMMIT();
    }

    for (int it = 0; it < niter; it++) {
        int st = it & (STAGES - 1);
        if (it + STAGES - 1 < niter) {
            int ns = (it + STAGES - 1) & (STAGES - 1);
            int k0 = (it + STAGES - 1) * BK2;
            CP16(smem_u32(&As[ns][r0][c8]), &A[(size_t)(bm + r0) * Kk + k0 + c8]);
            CP16(smem_u32(&As[ns][r1][c8]), &A[(size_t)(bm + r1) * Kk + k0 + c8]);
            CP16(smem_u32(&Ws[ns][r0][c8]), &W[(size_t)(bn + r0) * Kk + k0 + c8]);
            CP16(smem_u32(&Ws[ns][r1][c8]), &W[(size_t)(bn + r1) * Kk + k0 + c8]);
            CPCOMMIT();
            asm volatile("cp.async.wait_group %0;" :: "n"(STAGES - 1));
        } else if (it + 2 < niter) {
            asm volatile("cp.async.wait_group 2;");
        } else if (it + 1 < niter) {
            asm volatile("cp.async.wait_group 1;");
        } else {
            asm volatile("cp.async.wait_group 0;");
        }
        __syncthreads();

        uint32_t stA = aAddr + st * STAGE_BYTES;
        uint32_t stW = wAddr + st * STAGE_BYTES;
#pragma unroll
        for (int kh = 0; kh < 2; kh++) {      // two k=16 halves of BK=32
            int kb = kh * 16 * 2;             // byte offset within row
            uint32_t af[4][4];
#pragma unroll
            for (int mi = 0; mi < 4; mi++)
                LDSM4(af[mi][0], af[mi][1], af[mi][2], af[mi][3],
                      stA + mi * 16 * GSTR * 2 + kb);
            uint32_t b00, b01, b02, b03, b10, b11, b12, b13;
            LDSM4(b00, b01, b02, b03, stW + kb);                       // n 0-15
            LDSM4(b10, b11, b12, b13, stW + 16 * GSTR * 2 + kb);       // n 16-31
            uint32_t bf[4][2] = {{b00, b02}, {b01, b03}, {b10, b12}, {b11, b13}};
#pragma unroll
            for (int mi = 0; mi < 4; mi++)
#pragma unroll
                for (int ni = 0; ni < 4; ni++)
                    mma_bf16(acc[mi][ni], af[mi], bf[ni][0], bf[ni][1]);
        }
        __syncthreads();
    }

    // epilogue
#pragma unroll
    for (int mi = 0; mi < 4; mi++) {
#pragma unroll
        for (int ni = 0; ni < 4; ni++) {
            int rr0 = bm + wm + mi * 16 + lr;
            int cc = bn + wn + ni * 8 + 2 * lc;
            float b0 = bias[cc], b1 = bias[cc + 1];
#pragma unroll
            for (int half = 0; half < 2; half++) {
                int r = rr0 + half * 8;
                float v0 = acc[mi][ni][half * 2 + 0] + b0;
                float v1 = acc[mi][ni][half * 2 + 1] + b1;
                if (EPI == 1) {
                    v0 = 0.5f * v0 * (1.0f + erff(v0 * 0.70710678118654752f));
                    v1 = 0.5f * v1 * (1.0f + erff(v1 * 0.70710678118654752f));
                    __nv_bfloat162 hv = __floats2bfloat162_rn(v0, v1);
                    *(__nv_bfloat162*)((__nv_bfloat16*)Cv + (size_t)r * Nn + cc) = hv;
                } else {
                    if (EPI == 2) {
                        const float2 rv = *(const float2*)&resid[(size_t)r * Nn + cc];
                        v0 += rv.x; v1 += rv.y;
                    }
                    float2 ov = {v0, v1};
                    *(float2*)((float*)Cv + (size_t)r * Nn + cc) = ov;
                }
            }
        }
    }
}

// ==================== TF32 tensor-core flash attention =======================
// Block: 128 threads (4 warps). Each warp owns 16 queries; block owns 64 and
// shares K/V smem tiles of 32 kv. Online softmax with register fragments.
__global__ void __launch_bounds__(128) attn_mma(
        const float* __restrict__ Q, const float* __restrict__ K,
        const float* __restrict__ V, const float* __restrict__ X,
        float* __restrict__ O, int q_off, int kv_off, int kv_len) {
    int b = blockIdx.z, h = blockIdx.y;
    int t = threadIdx.x;
    int w = t >> 5, lane = t & 31;
    int lr = lane >> 2, lc = lane & 3;
    int qbase = q_off + blockIdx.x * 64 + w * 16;

    __shared__ __align__(16) uint32_t ks_sm[32][52];
    __shared__ __align__(16) uint32_t vt_sm[HDIM][36];
    __shared__ __align__(16) float ps_sm[4][16][36];

    // Q fragments, scale folded in; resident across kv loop
    uint32_t aq[6][4];
#pragma unroll
    for (int kd = 0; kd < 6; kd++) {
        const float* qp0 = &Q[((size_t)(b * NTOK + qbase + lr)) * DMODEL + h * HDIM + kd * 8 + lc];
        const float* qp1 = qp0 + 8 * DMODEL;
        aq[kd][0] = f2tf32(qp0[0] * ATT_SCALE);
        aq[kd][1] = f2tf32(qp1[0] * ATT_SCALE);
        aq[kd][2] = f2tf32(qp0[4] * ATT_SCALE);
        aq[kd][3] = f2tf32(qp1[4] * ATT_SCALE);
    }

    float oacc[6][4];
#pragma unroll
    for (int ni = 0; ni < 6; ni++)
#pragma unroll
        for (int f = 0; f < 4; f++) oacc[ni][f] = 0.f;
    float m0 = -1e30f, m1 = -1e30f, l0 = 0.f, l1 = 0.f;

    for (int kt = 0; kt < kv_len; kt += 32) {
        // load K tile (row-major tf32) and V tile transposed
#pragma unroll
        for (int i = 0; i < 3; i++) {
            int e = t + i * 128;
            int r = e / 12, cc4 = (e % 12) * 4;
            size_t g = ((size_t)(b * KVTOK + kv_off + kt + r)) * DMODEL + h * HDIM + cc4;
            float4 kv4 = *(const float4*)&K[g];
            uint4 ku = {f2tf32(kv4.x), f2tf32(kv4.y), f2tf32(kv4.z), f2tf32(kv4.w)};
            *(uint4*)&ks_sm[r][cc4] = ku;
            float4 vv4 = *(const float4*)&V[g];
            vt_sm[cc4 + 0][r] = f2tf32(vv4.x);
            vt_sm[cc4 + 1][r] = f2tf32(vv4.y);
            vt_sm[cc4 + 2][r] = f2tf32(vv4.z);
            vt_sm[cc4 + 3][r] = f2tf32(vv4.w);
        }
        __syncthreads();

        // S = Q @ K^T  (16 x 32)
        float sacc[4][4];
#pragma unroll
        for (int ni = 0; ni < 4; ni++)
#pragma unroll
            for (int f = 0; f < 4; f++) sacc[ni][f] = 0.f;
#pragma unroll
        for (int kd = 0; kd < 6; kd++) {
#pragma unroll
            for (int ni = 0; ni < 4; ni++) {
                uint32_t b0 = ks_sm[ni * 8 + lr][kd * 8 + lc];
                uint32_t b1 = ks_sm[ni * 8 + lr][kd * 8 + lc + 4];
                mma_tf32(sacc[ni], aq[kd], b0, b1);
            }
        }

        // online softmax on fragments (rows lr and lr+8)
        float mt0 = -1e30f, mt1 = -1e30f;
#pragma unroll
        for (int ni = 0; ni < 4; ni++) {
            mt0 = fmaxf(mt0, fmaxf(sacc[ni][0], sacc[ni][1]));
            mt1 = fmaxf(mt1, fmaxf(sacc[ni][2], sacc[ni][3]));
        }
        mt0 = fmaxf(mt0, __shfl_xor_sync(0xffffffffu, mt0, 1));
        mt0 = fmaxf(mt0, __shfl_xor_sync(0xffffffffu, mt0, 2));
        mt1 = fmaxf(mt1, __shfl_xor_sync(0xffffffffu, mt1, 1));
        mt1 = fmaxf(mt1, __shfl_xor_sync(0xffffffffu, mt1, 2));
        float mn0 = fmaxf(m0, mt0), mn1 = fmaxf(m1, mt1);
        float cr0 = __expf(m0 - mn0), cr1 = __expf(m1 - mn1);
        float ps0 = 0.f, ps1 = 0.f;
#pragma unroll
        for (int ni = 0; ni < 4; ni++) {
            float p00 = __expf(sacc[ni][0] - mn0);
            float p01 = __expf(sacc[ni][1] - mn0);
            float p10 = __expf(sacc[ni][2] - mn1);
            float p11 = __expf(sacc[ni][3] - mn1);
            ps0 += p00 + p01; ps1 += p10 + p11;
            float2 w0 = {p00, p01};
            float2 w1 = {p10, p11};
            *(float2*)&ps_sm[w][lr][ni * 8 + 2 * lc] = w0;
            *(float2*)&ps_sm[w][lr + 8][ni * 8 + 2 * lc] = w1;
        }
        ps0 += __shfl_xor_sync(0xffffffffu, ps0, 1);
        ps0 += __shfl_xor_sync(0xffffffffu, ps0, 2);
        ps1 += __shfl_xor_sync(0xffffffffu, ps1, 1);
        ps1 += __shfl_xor_sync(0xffffffffu, ps1, 2);
        l0 = l0 * cr0 + ps0;
        l1 = l1 * cr1 + ps1;
        m0 = mn0; m1 = mn1;
#pragma unroll
        for (int ni = 0; ni < 6; ni++) {
            oacc[ni][0] *= cr0; oacc[ni][1] *= cr0;
            oacc[ni][2] *= cr1; oacc[ni][3] *= cr1;
        }
        __syncwarp();

        // O += P @ V   (16 x 48, k = 32)
#pragma unroll
        for (int kd = 0; kd < 4; kd++) {
            uint32_t ap[4];
            ap[0] = f2tf32(ps_sm[w][lr][kd * 8 + lc]);
            ap[1] = f2tf32(ps_sm[w][lr + 8][kd * 8 + lc]);
            ap[2] = f2tf32(ps_sm[w][lr][kd * 8 + lc + 4]);
            ap[3] = f2tf32(ps_sm[w][lr + 8][kd * 8 + lc + 4]);
#pragma unroll
            for (int ni = 0; ni < 6; ni++) {
                uint32_t b0 = vt_sm[ni * 8 + lr][kd * 8 + lc];
                uint32_t b1 = vt_sm[ni * 8 + lr][kd * 8 + lc + 4];
                mma_tf32(oacc[ni], ap, b0, b1);
            }
        }
        __syncthreads();
    }

    float rc0 = 1.0f / l0, rc1 = 1.0f / l1;
#pragma unroll
    for (int ni = 0; ni < 6; ni++) {
        int col = h * HDIM + ni * 8 + 2 * lc;
        size_t g0 = ((size_t)(b * NTOK + qbase + lr)) * DMODEL + col;
        size_t g1 = g0 + (size_t)8 * DMODEL;
        float2 x0 = *(const float2*)&X[g0];
        float2 x1 = *(const float2*)&X[g1];
        float2 o0 = {x0.x + oacc[ni][0] * rc0, x0.y + oacc[ni][1] * rc0};
        float2 o1 = {x1.x + oacc[ni][2] * rc1, x1.y + oacc[ni][3] * rc1};
        *(float2*)&O[g0] = o0;
        *(float2*)&O[g1] = o1;
    }
}

// ================================ launch =====================================
extern "C" void kernel_launch(void* const* d_in, const int* in_sizes, int n_in,
                              void* d_out, int out_size) {
    const float* x     = (const float*)d_in[0];
    const float* ln1_g = (const float*)d_in[1];
    const float* ln1_b = (const float*)d_in[2];
    const float* dwq_w = (const float*)d_in[3];
    const float* dwq_b = (const float*)d_in[4];
    const float* bnq_g = (const float*)d_in[5];
    const float* bnq_b = (const float*)d_in[6];
    const float* dwk_w = (const float*)d_in[7];
    const float* dwk_b = (const float*)d_in[8];
    const float* bnk_g = (const float*)d_in[9];
    const float* bnk_b = (const float*)d_in[10];
    const float* dwv_w = (const float*)d_in[11];
    const float* dwv_b = (const float*)d_in[12];
    const float* bnv_g = (const float*)d_in[13];
    const float* bnv_b = (const float*)d_in[14];
    const float* pq_w  = (const float*)d_in[15];
    const float* pq_b  = (const float*)d_in[16];
    const float* pk_w  = (const float*)d_in[17];
    const float* pk_b  = (const float*)d_in[18];
    const float* pv_w  = (const float*)d_in[19];
    const float* pv_b  = (const float*)d_in[20];
    const float* ln2_g = (const float*)d_in[21];
    const float* ln2_b = (const float*)d_in[22];
    const float* ff1_w = (const float*)d_in[23];
    const float* ff1_b = (const float*)d_in[24];
    const float* ff2_w = (const float*)d_in[25];
    const float* ff2_b = (const float*)d_in[26];
    float* out = (float*)d_out;

    float *xn, *q, *k, *v, *x1;
    __nv_bfloat16 *cq, *ck, *cv, *l2, *hbuf;
    __nv_bfloat16 *wq, *wk, *wv, *w1, *w2;
    cudaGetSymbolAddress((void**)&xn,   g_xn);
    cudaGetSymbolAddress((void**)&cq,   g_cq);
    cudaGetSymbolAddress((void**)&ck,   g_ck);
    cudaGetSymbolAddress((void**)&cv,   g_cv);
    cudaGetSymbolAddress((void**)&q,    g_q);
    cudaGetSymbolAddress((void**)&k,    g_k);
    cudaGetSymbolAddress((void**)&v,    g_v);
    cudaGetSymbolAddress((void**)&x1,   g_x1);
    cudaGetSymbolAddress((void**)&l2,   g_l2);
    cudaGetSymbolAddress((void**)&hbuf, g_h);
    cudaGetSymbolAddress((void**)&wq,   g_wq);
    cudaGetSymbolAddress((void**)&wk,   g_wk);
    cudaGetSymbolAddress((void**)&wv,   g_wv);
    cudaGetSymbolAddress((void**)&w1,   g_w1);
    cudaGetSymbolAddress((void**)&w2,   g_w2);

    cudaFuncSetAttribute(gemm_tc<0>, cudaFuncAttributeMaxDynamicSharedMemorySize, GEMM_SMEM);
    cudaFuncSetAttribute(gemm_tc<1>, cudaFuncAttributeMaxDynamicSharedMemorySize, GEMM_SMEM);
    cudaFuncSetAttribute(gemm_tc<2>, cudaFuncAttributeMaxDynamicSharedMemorySize, GEMM_SMEM);

    const int Mq = BATCH * NTOK;    // 40960
    const int Mkv = BATCH * KVTOK;  // 10240
    const int NDD = DMODEL * DMODEL;
    const int NFD = FFDIM * DMODEL;

    // weight pre-round to bf16 (runs every call for determinism)
    cvt_kernel<<<(NDD + 255) / 256, 256>>>(pq_w, wq, NDD);
    cvt_kernel<<<(NDD + 255) / 256, 256>>>(pk_w, wk, NDD);
    cvt_kernel<<<(NDD + 255) / 256, 256>>>(pv_w, wv, NDD);
    cvt_kernel<<<(NFD + 255) / 256, 256>>>(ff1_w, w1, NFD);
    cvt_kernel<<<(NFD + 255) / 256, 256>>>(ff2_w, w2, NFD);

    ln_kernel<float><<<Mq, 128>>>(x, ln1_g, ln1_b, xn);
    convq_kernel<<<dim3(NTOK, BATCH), DMODEL>>>(xn, dwq_w, dwq_b, bnq_g, bnq_b, cq);
    convkv_kernel<<<dim3(KVTOK, BATCH), DMODEL>>>(xn, dwk_w, dwk_b, bnk_g, bnk_b,
                                                  dwv_w, dwv_b, bnv_g, bnv_b, ck, cv);
    gemm_tc<0><<<dim3(DMODEL / BN, Mq / BM), 256, GEMM_SMEM>>>(cq, wq, pq_b, nullptr, q, Mq, DMODEL, DMODEL);
    gemm_tc<0><<<dim3(DMODEL / BN, Mkv / BM), 256, GEMM_SMEM>>>(ck, wk, pk_b, nullptr, k, Mkv, DMODEL, DMODEL);
    gemm_tc<0><<<dim3(DMODEL / BN, Mkv / BM), 256, GEMM_SMEM>>>(cv, wv, pv_b, nullptr, v, Mkv, DMODEL, DMODEL);
    attn_mma<<<dim3(NS_TOK / 64, NHEAD, BATCH), 128>>>(q, k, v, x, x1, 0, 0, KVTOK);
    attn_mma<<<dim3(NT_TOK / 64, NHEAD, BATCH), 128>>>(q, k, v, x, x1, NS_TOK, KV_S, KV_T);
    ln_kernel<__nv_bfloat16><<<Mq, 128>>>(x1, ln2_g, ln2_b, l2);
    gemm_tc<1><<<dim3(FFDIM / BN, Mq / BM), 256, GEMM_SMEM>>>(l2, w1, ff1_b, nullptr, hbuf, Mq, FFDIM, DMODEL);
    gemm_tc<2><<<dim3(DMODEL / BN, Mq / BM), 256, GEMM_SMEM>>>(hbuf, w2, ff2_b, x1, out, Mq, DMODEL, FFDIM);
}

// round 15
// speedup vs baseline: 1.3730x; 1.0091x over previous
#include <cuda_runtime.h>
#include <cuda_bf16.h>
#include <math.h>
#include <stdint.h>

// Problem constants
#define BATCH 32
#define DMODEL 384
#define NHEAD 8
#define HDIM 48
#define NS_TOK 1024
#define NT_TOK 256
#define NTOK 1280
#define KV_S 256
#define KV_T 64
#define KVTOK 320
#define FFDIM 1536
#define ATT_SCALE 0.14433756729740643f  // 1/sqrt(48)
#define EPS_LN 1e-5f
#define EPS_BN 1e-5f

// -------- scratch (device globals; no allocation allowed) --------
__device__ float g_xn[(size_t)BATCH * NTOK * DMODEL];
__device__ __nv_bfloat16 g_cq[(size_t)BATCH * NTOK * DMODEL];
__device__ __nv_bfloat16 g_ck[(size_t)BATCH * KVTOK * DMODEL];
__device__ __nv_bfloat16 g_cv[(size_t)BATCH * KVTOK * DMODEL];
__device__ float g_q [(size_t)BATCH * NTOK * DMODEL];
__device__ float g_k [(size_t)BATCH * KVTOK * DMODEL];
__device__ float g_v [(size_t)BATCH * KVTOK * DMODEL];
__device__ float g_x1[(size_t)BATCH * NTOK * DMODEL];
__device__ __nv_bfloat16 g_l2[(size_t)BATCH * NTOK * DMODEL];
__device__ __nv_bfloat16 g_h [(size_t)BATCH * NTOK * FFDIM];
// bf16-pre-rounded weights
__device__ __nv_bfloat16 g_wq[DMODEL * DMODEL];
__device__ __nv_bfloat16 g_wk[DMODEL * DMODEL];
__device__ __nv_bfloat16 g_wv[DMODEL * DMODEL];
__device__ __nv_bfloat16 g_w1[FFDIM * DMODEL];
__device__ __nv_bfloat16 g_w2[DMODEL * FFDIM];

// ---------------- helpers ----------------
__device__ __forceinline__ uint32_t f2tf32(float x) {
    uint32_t u;
    asm("cvt.rna.tf32.f32 %0, %1;" : "=r"(u) : "f"(x));
    return u;
}
__device__ __forceinline__ uint32_t smem_u32(const void* p) {
    return (uint32_t)__cvta_generic_to_shared(p);
}
#define CP16(dst, src) asm volatile("cp.async.cg.shared.global [%0], [%1], 16;" :: "r"(dst), "l"(src))
#define CPCOMMIT() asm volatile("cp.async.commit_group;")
#define LDSM4(d0, d1, d2, d3, addr) \
    asm volatile("ldmatrix.sync.aligned.m8n8.x4.shared.b16 {%0,%1,%2,%3}, [%4];" \
                 : "=r"(d0), "=r"(d1), "=r"(d2), "=r"(d3) : "r"(addr))

__device__ __forceinline__ void mma_tf32(float* c, const uint32_t* a, uint32_t b0, uint32_t b1) {
    asm volatile(
        "mma.sync.aligned.m16n8k8.row.col.f32.tf32.tf32.f32 "
        "{%0,%1,%2,%3}, {%4,%5,%6,%7}, {%8,%9}, {%0,%1,%2,%3};\n"
        : "+f"(c[0]), "+f"(c[1]), "+f"(c[2]), "+f"(c[3])
        : "r"(a[0]), "r"(a[1]), "r"(a[2]), "r"(a[3]), "r"(b0), "r"(b1));
}
__device__ __forceinline__ void mma_bf16(float* c, const uint32_t* a, uint32_t b0, uint32_t b1) {
    asm volatile(
        "mma.sync.aligned.m16n8k16.row.col.f32.bf16.bf16.f32 "
        "{%0,%1,%2,%3}, {%4,%5,%6,%7}, {%8,%9}, {%0,%1,%2,%3};\n"
        : "+f"(c[0]), "+f"(c[1]), "+f"(c[2]), "+f"(c[3])
        : "r"(a[0]), "r"(a[1]), "r"(a[2]), "r"(a[3]), "r"(b0), "r"(b1));
}

// ============== weight pre-round to bf16 (elementwise) =======================
__global__ void cvt_kernel(const float* __restrict__ src, __nv_bfloat16* __restrict__ dst, int n) {
    int i = blockIdx.x * 256 + threadIdx.x;
    if (i < n) dst[i] = __float2bfloat16(src[i]);
}

// ======================= LayerNorm (one block / token) =======================
template<typename OUT>
__global__ void ln_kernel(const float* __restrict__ X, const float* __restrict__ gg,
                          const float* __restrict__ bb, OUT* __restrict__ Y) {
    int row = blockIdx.x, t = threadIdx.x;   // 128 threads
    const float* xp = X + (size_t)row * DMODEL;
    float v[3];
    float s = 0.f, ss = 0.f;
#pragma unroll
    for (int i = 0; i < 3; i++) { v[i] = xp[t + i * 128]; s += v[i]; ss += v[i] * v[i]; }
#pragma unroll
    for (int off = 16; off > 0; off >>= 1) {
        s  += __shfl_xor_sync(0xffffffffu, s,  off);
        ss += __shfl_xor_sync(0xffffffffu, ss, off);
    }
    __shared__ float sm[4], sm2[4];
    int wid = t >> 5;
    if ((t & 31) == 0) { sm[wid] = s; sm2[wid] = ss; }
    __syncthreads();
    s  = sm[0] + sm[1] + sm[2] + sm[3];
    ss = sm2[0] + sm2[1] + sm2[2] + sm2[3];
    float mean = s * (1.0f / DMODEL);
    float var  = ss * (1.0f / DMODEL) - mean * mean;
    float r = rsqrtf(var + EPS_LN);
    OUT* yp = Y + (size_t)row * DMODEL;
#pragma unroll
    for (int i = 0; i < 3; i++) {
        int c = t + i * 128;
        yp[c] = (OUT)((v[i] - mean) * r * gg[c] + bb[c]);
    }
}

// ================= Depthwise 3x3 conv + BN, stride 1 (Q path) ================
__global__ void convq_kernel(const float* __restrict__ xn, const float* __restrict__ w,
                             const float* __restrict__ cb, const float* __restrict__ g,
                             const float* __restrict__ bb, __nv_bfloat16* __restrict__ out) {
    int b = blockIdx.y, tok = blockIdx.x, c = threadIdx.x;
    int Wd, base;
    if (tok < NS_TOK) { Wd = 32; base = 0; } else { Wd = 16; base = NS_TOK; }
    int loc = tok - base;
    int oy = loc / Wd, ox = loc % Wd;
    const float* wp = w + c * 9;
    float acc = 0.f;
#pragma unroll
    for (int ky = 0; ky < 3; ky++) {
        int iy = oy - 1 + ky;
        if (iy < 0 || iy >= Wd) continue;
#pragma unroll
        for (int kx = 0; kx < 3; kx++) {
            int ix = ox - 1 + kx;
            if (ix < 0 || ix >= Wd) continue;
            acc += wp[ky * 3 + kx] * xn[((size_t)b * NTOK + base + iy * Wd + ix) * DMODEL + c];
        }
    }
    float sc = g[c] * rsqrtf(1.0f + EPS_BN);
    out[((size_t)b * NTOK + tok) * DMODEL + c] = __float2bfloat16((acc + cb[c]) * sc + bb[c]);
}

// ============ Depthwise 3x3 conv + BN, stride 2, fused K & V =================
__global__ void convkv_kernel(const float* __restrict__ xn,
                              const float* __restrict__ wk, const float* __restrict__ cbk,
                              const float* __restrict__ gk, const float* __restrict__ bbk,
                              const float* __restrict__ wv, const float* __restrict__ cbv,
                              const float* __restrict__ gv, const float* __restrict__ bbv,
                              __nv_bfloat16* __restrict__ outk, __nv_bfloat16* __restrict__ outv) {
    int b = blockIdx.y, tok = blockIdx.x, c = threadIdx.x;
    int Wd, inW, inBase, base;
    if (tok < KV_S) { Wd = 16; inW = 32; inBase = 0; base = 0; }
    else            { Wd = 8;  inW = 16; inBase = NS_TOK; base = KV_S; }
    int loc = tok - base;
    int oy = loc / Wd, ox = loc % Wd;
    const float* wpk = wk + c * 9;
    const float* wpv = wv + c * 9;
    float acck = 0.f, accv = 0.f;
#pragma unroll
    for (int ky = 0; ky < 3; ky++) {
        int iy = 2 * oy - 1 + ky;
        if (iy < 0 || iy >= inW) continue;
#pragma unroll
        for (int kx = 0; kx < 3; kx++) {
            int ix = 2 * ox - 1 + kx;
            if (ix < 0 || ix >= inW) continue;
            float xv = xn[((size_t)b * NTOK + inBase + iy * inW + ix) * DMODEL + c];
            acck += wpk[ky * 3 + kx] * xv;
            accv += wpv[ky * 3 + kx] * xv;
        }
    }
    size_t oidx = ((size_t)b * KVTOK + tok) * DMODEL + c;
    outk[oidx] = __float2bfloat16((acck + cbk[c]) * (gk[c] * rsqrtf(1.0f + EPS_BN)) + bbk[c]);
    outv[oidx] = __float2bfloat16((accv + cbv[c]) * (gv[c] * rsqrtf(1.0f + EPS_BN)) + bbv[c]);
}

// ========== BF16 tensor-core GEMM, 4-stage cp.async + ldmatrix ===============
// C = A @ W^T + bias. A[M,K], W[N,K] row-major bf16. 128x128 tile, BK=32,
// 4 stages, 8 warps (2x4), warp tile 64x32, mma m16n8k16.
// EPI: 0 -> fp32 out; 1 -> gelu, bf16 out; 2 -> +resid(fp32), fp32 out.
#define BM 128
#define BN 128
#define BK2 32
#define GSTR 40            // bf16 per smem row (32 + 8 pad) = 80 bytes
#define STAGES 4
#define STAGE_BYTES (128 * GSTR * 2)   // 10240 B
#define GEMM_SMEM (STAGES * STAGE_BYTES * 2)

template<int EPI>
__global__ void __launch_bounds__(256) gemm_tc(
        const __nv_bfloat16* __restrict__ A, const __nv_bfloat16* __restrict__ W,
        const float* __restrict__ bias, const float* __restrict__ resid,
        void* __restrict__ Cv, int M, int Nn, int Kk) {
    extern __shared__ __align__(16) char smraw[];
    __nv_bfloat16 (*As)[BM][GSTR] = (__nv_bfloat16(*)[BM][GSTR])smraw;
    __nv_bfloat16 (*Ws)[BN][GSTR] = (__nv_bfloat16(*)[BN][GSTR])(smraw + STAGES * STAGE_BYTES);

    int t = threadIdx.x;
    int lane = t & 31, wid = t >> 5;
    int wm = (wid & 1) * 64;
    int wn = (wid >> 1) * 32;
    int bm = blockIdx.y * BM, bn = blockIdx.x * BN;
    int lr = lane >> 2, lc = lane & 3;

    float acc[4][4][4];
#pragma unroll
    for (int mi = 0; mi < 4; mi++)
#pragma unroll
        for (int ni = 0; ni < 4; ni++)
#pragma unroll
            for (int f = 0; f < 4; f++) acc[mi][ni][f] = 0.f;

    // cp.async coords: row = t>>2 (+64), 16B chunk = (t&3)*8 bf16
    int r0 = t >> 2, c8 = (t & 3) * 8;
    int r1 = r0 + 64;

    // ldmatrix per-lane base addresses
    int arow = wm + (lane & 7) + ((lane >> 3) & 1) * 8;
    int acol = ((lane >> 4) & 1) * 8;   // bf16 units (16 bytes)
    uint32_t aAddr = smem_u32(&As[0][arow][acol]);
    int brow = wn + (lane & 7) + ((lane >> 3) & 1) * 8;
    int bcol = ((lane >> 4) & 1) * 8;
    uint32_t wAddr = smem_u32(&Ws[0][brow][bcol]);

    int niter = Kk / BK2;
    // prologue: stages 0..2
#pragma unroll
    for (int p = 0; p < STAGES - 1; p++) {
        int k0 = p * BK2;
        CP16(smem_u32(&As[p][r0][c8]), &A[(size_t)(bm + r0) * Kk + k0 + c8]);
        CP16(smem_u32(&As[p][r1][c8]), &A[(size_t)(bm + r1) * Kk + k0 + c8]);
        CP16(smem_u32(&Ws[p][r0][c8]), &W[(size_t)(bn + r0) * Kk + k0 + c8]);
        CP16(smem_u32(&Ws[p][r1][c8]), &W[(size_t)(bn + r1) * Kk + k0 + c8]);
        CPCOMMIT();
    }

    for (int it = 0; it < niter; it++) {
        int st = it & (STAGES - 1);
        if (it + STAGES - 1 < niter) {
            int ns = (it + STAGES - 1) & (STAGES - 1);
            int k0 = (it + STAGES - 1) * BK2;
            CP16(smem_u32(&As[ns][r0][c8]), &A[(size_t)(bm + r0) * Kk + k0 + c8]);
            CP16(smem_u32(&As[ns][r1][c8]), &A[(size_t)(bm + r1) * Kk + k0 + c8]);
            CP16(smem_u32(&Ws[ns][r0][c8]), &W[(size_t)(bn + r0) * Kk + k0 + c8]);
            CP16(smem_u32(&Ws[ns][r1][c8]), &W[(size_t)(bn + r1) * Kk + k0 + c8]);
            CPCOMMIT();
            asm volatile("cp.async.wait_group %0;" :: "n"(STAGES - 1));
        } else if (it + 2 < niter) {
            asm volatile("cp.async.wait_group 2;");
        } else if (it + 1 < niter) {
            asm volatile("cp.async.wait_group 1;");
        } else {
            asm volatile("cp.async.wait_group 0;");
        }
        __syncthreads();

        uint32_t stA = aAddr + st * STAGE_BYTES;
        uint32_t stW = wAddr + st * STAGE_BYTES;
#pragma unroll
        for (int kh = 0; kh < 2; kh++) {      // two k=16 halves of BK=32
            int kb = kh * 16 * 2;             // byte offset within row
            uint32_t af[4][4];
#pragma unroll
            for (int mi = 0; mi < 4; mi++)
                LDSM4(af[mi][0], af[mi][1], af[mi][2], af[mi][3],
                      stA + mi * 16 * GSTR * 2 + kb);
            uint32_t b00, b01, b02, b03, b10, b11, b12, b13;
            LDSM4(b00, b01, b02, b03, stW + kb);                       // n 0-15
            LDSM4(b10, b11, b12, b13, stW + 16 * GSTR * 2 + kb);       // n 16-31
            uint32_t bf[4][2] = {{b00, b02}, {b01, b03}, {b10, b12}, {b11, b13}};
#pragma unroll
            for (int mi = 0; mi < 4; mi++)
#pragma unroll
                for (int ni = 0; ni < 4; ni++)
                    mma_bf16(acc[mi][ni], af[mi], bf[ni][0], bf[ni][1]);
        }
        __syncthreads();
    }

    // epilogue
#pragma unroll
    for (int mi = 0; mi < 4; mi++) {
#pragma unroll
        for (int ni = 0; ni < 4; ni++) {
            int rr0 = bm + wm + mi * 16 + lr;
            int cc = bn + wn + ni * 8 + 2 * lc;
            float b0 = bias[cc], b1 = bias[cc + 1];
#pragma unroll
            for (int half = 0; half < 2; half++) {
                int r = rr0 + half * 8;
                float v0 = acc[mi][ni][half * 2 + 0] + b0;
                float v1 = acc[mi][ni][half * 2 + 1] + b1;
                if (EPI == 1) {
                    v0 = 0.5f * v0 * (1.0f + erff(v0 * 0.70710678118654752f));
                    v1 = 0.5f * v1 * (1.0f + erff(v1 * 0.70710678118654752f));
                    __nv_bfloat162 hv = __floats2bfloat162_rn(v0, v1);
                    *(__nv_bfloat162*)((__nv_bfloat16*)Cv + (size_t)r * Nn + cc) = hv;
                } else {
                    if (EPI == 2) {
                        const float2 rv = *(const float2*)&resid[(size_t)r * Nn + cc];
                        v0 += rv.x; v1 += rv.y;
                    }
                    float2 ov = {v0, v1};
                    *(float2*)((float*)Cv + (size_t)r * Nn + cc) = ov;
                }
            }
        }
    }
}

// ==================== TF32 tensor-core flash attention =======================
// Block: 128 threads (4 warps). Each warp owns 16 queries; block owns 64 and
// shares K/V smem tiles of 32 kv. Register double-buffering: next kv tile is
// prefetched into registers while the current tile is being computed.
__global__ void __launch_bounds__(128) attn_mma(
        const float* __restrict__ Q, const float* __restrict__ K,
        const float* __restrict__ V, const float* __restrict__ X,
        float* __restrict__ O, int q_off, int kv_off, int kv_len) {
    int b = blockIdx.z, h = blockIdx.y;
    int t = threadIdx.x;
    int w = t >> 5, lane = t & 31;
    int lr = lane >> 2, lc = lane & 3;
    int qbase = q_off + blockIdx.x * 64 + w * 16;

    __shared__ __align__(16) uint32_t ks_sm[32][52];
    __shared__ __align__(16) uint32_t vt_sm[HDIM][36];
    __shared__ __align__(16) float ps_sm[4][16][36];

    // per-thread kv-tile load coords (3 float4 per matrix per tile)
    int ldr[3], ldc[3];
#pragma unroll
    for (int i = 0; i < 3; i++) {
        int e = t + i * 128;
        ldr[i] = e / 12;
        ldc[i] = (e % 12) * 4;
    }

    // Q fragments, scale folded in; resident across kv loop
    uint32_t aq[6][4];
#pragma unroll
    for (int kd = 0; kd < 6; kd++) {
        const float* qp0 = &Q[((size_t)(b * NTOK + qbase + lr)) * DMODEL + h * HDIM + kd * 8 + lc];
        const float* qp1 = qp0 + 8 * DMODEL;
        aq[kd][0] = f2tf32(qp0[0] * ATT_SCALE);
        aq[kd][1] = f2tf32(qp1[0] * ATT_SCALE);
        aq[kd][2] = f2tf32(qp0[4] * ATT_SCALE);
        aq[kd][3] = f2tf32(qp1[4] * ATT_SCALE);
    }

    float oacc[6][4];
#pragma unroll
    for (int ni = 0; ni < 6; ni++)
#pragma unroll
        for (int f = 0; f < 4; f++) oacc[ni][f] = 0.f;
    float m0 = -1e30f, m1 = -1e30f, l0 = 0.f, l1 = 0.f;

    // prologue: load tile 0 into registers
    float4 kreg[3], vreg[3];
#pragma unroll
    for (int i = 0; i < 3; i++) {
        size_t g = ((size_t)(b * KVTOK + kv_off + ldr[i])) * DMODEL + h * HDIM + ldc[i];
        kreg[i] = *(const float4*)&K[g];
        vreg[i] = *(const float4*)&V[g];
    }

    for (int kt = 0; kt < kv_len; kt += 32) {
        // store prefetched tile to smem (K row-major tf32, V transposed)
#pragma unroll
        for (int i = 0; i < 3; i++) {
            int r = ldr[i], cc4 = ldc[i];
            uint4 ku = {f2tf32(kreg[i].x), f2tf32(kreg[i].y), f2tf32(kreg[i].z), f2tf32(kreg[i].w)};
            *(uint4*)&ks_sm[r][cc4] = ku;
            vt_sm[cc4 + 0][r] = f2tf32(vreg[i].x);
            vt_sm[cc4 + 1][r] = f2tf32(vreg[i].y);
            vt_sm[cc4 + 2][r] = f2tf32(vreg[i].z);
            vt_sm[cc4 + 3][r] = f2tf32(vreg[i].w);
        }
        __syncthreads();

        // prefetch NEXT tile into registers (overlaps with compute below)
        if (kt + 32 < kv_len) {
#pragma unroll
            for (int i = 0; i < 3; i++) {
                size_t g = ((size_t)(b * KVTOK + kv_off + kt + 32 + ldr[i])) * DMODEL + h * HDIM + ldc[i];
                kreg[i] = *(const float4*)&K[g];
                vreg[i] = *(const float4*)&V[g];
            }
        }

        // S = Q @ K^T  (16 x 32)
        float sacc[4][4];
#pragma unroll
        for (int ni = 0; ni < 4; ni++)
#pragma unroll
            for (int f = 0; f < 4; f++) sacc[ni][f] = 0.f;
#pragma unroll
        for (int kd = 0; kd < 6; kd++) {
#pragma unroll
            for (int ni = 0; ni < 4; ni++) {
                uint32_t b0 = ks_sm[ni * 8 + lr][kd * 8 + lc];
                uint32_t b1 = ks_sm[ni * 8 + lr][kd * 8 + lc + 4];
                mma_tf32(sacc[ni], aq[kd], b0, b1);
            }
        }

        // online softmax on fragments (rows lr and lr+8)
        float mt0 = -1e30f, mt1 = -1e30f;
#pragma unroll
        for (int ni = 0; ni < 4; ni++) {
            mt0 = fmaxf(mt0, fmaxf(sacc[ni][0], sacc[ni][1]));
            mt1 = fmaxf(mt1, fmaxf(sacc[ni][2], sacc[ni][3]));
        }
        mt0 = fmaxf(mt0, __shfl_xor_sync(0xffffffffu, mt0, 1));
        mt0 = fmaxf(mt0, __shfl_xor_sync(0xffffffffu, mt0, 2));
        mt1 = fmaxf(mt1, __shfl_xor_sync(0xffffffffu, mt1, 1));
        mt1 = fmaxf(mt1, __shfl_xor_sync(0xffffffffu, mt1, 2));
        float mn0 = fmaxf(m0, mt0), mn1 = fmaxf(m1, mt1);
        float cr0 = __expf(m0 - mn0), cr1 = __expf(m1 - mn1);
        float ps0 = 0.f, ps1 = 0.f;
#pragma unroll
        for (int ni = 0; ni < 4; ni++) {
            float p00 = __expf(sacc[ni][0] - mn0);
            float p01 = __expf(sacc[ni][1] - mn0);
            float p10 = __expf(sacc[ni][2] - mn1);
            float p11 = __expf(sacc[ni][3] - mn1);
            ps0 += p00 + p01; ps1 += p10 + p11;
            float2 w0 = {p00, p01};
            float2 w1 = {p10, p11};
            *(float2*)&ps_sm[w][lr][ni * 8 + 2 * lc] = w0;
            *(float2*)&ps_sm[w][lr + 8][ni * 8 + 2 * lc] = w1;
        }
        ps0 += __shfl_xor_sync(0xffffffffu, ps0, 1);
        ps0 += __shfl_xor_sync(0xffffffffu, ps0, 2);
        ps1 += __shfl_xor_sync(0xffffffffu, ps1, 1);
        ps1 += __shfl_xor_sync(0xffffffffu, ps1, 2);
        l0 = l0 * cr0 + ps0;
        l1 = l1 * cr1 + ps1;
        m0 = mn0; m1 = mn1;
#pragma unroll
        for (int ni = 0; ni < 6; ni++) {
            oacc[ni][0] *= cr0; oacc[ni][1] *= cr0;
            oacc[ni][2] *= cr1; oacc[ni][3] *= cr1;
        }
        __syncwarp();

        // O += P @ V   (16 x 48, k = 32)
#pragma unroll
        for (int kd = 0; kd < 4; kd++) {
            uint32_t ap[4];
            ap[0] = f2tf32(ps_sm[w][lr][kd * 8 + lc]);
            ap[1] = f2tf32(ps_sm[w][lr + 8][kd * 8 + lc]);
            ap[2] = f2tf32(ps_sm[w][lr][kd * 8 + lc + 4]);
            ap[3] = f2tf32(ps_sm[w][lr + 8][kd * 8 + lc + 4]);
#pragma unroll
            for (int ni = 0; ni < 6; ni++) {
                uint32_t b0 = vt_sm[ni * 8 + lr][kd * 8 + lc];
                uint32_t b1 = vt_sm[ni * 8 + lr][kd * 8 + lc + 4];
                mma_tf32(oacc[ni], ap, b0, b1);
            }
        }
        __syncthreads();
    }

    float rc0 = 1.0f / l0, rc1 = 1.0f / l1;
#pragma unroll
    for (int ni = 0; ni < 6; ni++) {
        int col = h * HDIM + ni * 8 + 2 * lc;
        size_t g0 = ((size_t)(b * NTOK + qbase + lr)) * DMODEL + col;
        size_t g1 = g0 + (size_t)8 * DMODEL;
        float2 x0 = *(const float2*)&X[g0];
        float2 x1 = *(const float2*)&X[g1];
        float2 o0 = {x0.x + oacc[ni][0] * rc0, x0.y + oacc[ni][1] * rc0};
        float2 o1 = {x1.x + oacc[ni][2] * rc1, x1.y + oacc[ni][3] * rc1};
        *(float2*)&O[g0] = o0;
        *(float2*)&O[g1] = o1;
    }
}

// ================================ launch =====================================
extern "C" void kernel_launch(void* const* d_in, const int* in_sizes, int n_in,
                              void* d_out, int out_size) {
    const float* x     = (const float*)d_in[0];
    const float* ln1_g = (const float*)d_in[1];
    const float* ln1_b = (const float*)d_in[2];
    const float* dwq_w = (const float*)d_in[3];
    const float* dwq_b = (const float*)d_in[4];
    const float* bnq_g = (const float*)d_in[5];
    const float* bnq_b = (const float*)d_in[6];
    const float* dwk_w = (const float*)d_in[7];
    const float* dwk_b = (const float*)d_in[8];
    const float* bnk_g = (const float*)d_in[9];
    const float* bnk_b = (const float*)d_in[10];
    const float* dwv_w = (const float*)d_in[11];
    const float* dwv_b = (const float*)d_in[12];
    const float* bnv_g = (const float*)d_in[13];
    const float* bnv_b = (const float*)d_in[14];
    const float* pq_w  = (const float*)d_in[15];
    const float* pq_b  = (const float*)d_in[16];
    const float* pk_w  = (const float*)d_in[17];
    const float* pk_b  = (const float*)d_in[18];
    const float* pv_w  = (const float*)d_in[19];
    const float* pv_b  = (const float*)d_in[20];
    const float* ln2_g = (const float*)d_in[21];
    const float* ln2_b = (const float*)d_in[22];
    const float* ff1_w = (const float*)d_in[23];
    const float* ff1_b = (const float*)d_in[24];
    const float* ff2_w = (const float*)d_in[25];
    const float* ff2_b = (const float*)d_in[26];
    float* out = (float*)d_out;

    float *xn, *q, *k, *v, *x1;
    __nv_bfloat16 *cq, *ck, *cv, *l2, *hbuf;
    __nv_bfloat16 *wq, *wk, *wv, *w1, *w2;
    cudaGetSymbolAddress((void**)&xn,   g_xn);
    cudaGetSymbolAddress((void**)&cq,   g_cq);
    cudaGetSymbolAddress((void**)&ck,   g_ck);
    cudaGetSymbolAddress((void**)&cv,   g_cv);
    cudaGetSymbolAddress((void**)&q,    g_q);
    cudaGetSymbolAddress((void**)&k,    g_k);
    cudaGetSymbolAddress((void**)&v,    g_v);
    cudaGetSymbolAddress((void**)&x1,   g_x1);
    cudaGetSymbolAddress((void**)&l2,   g_l2);
    cudaGetSymbolAddress((void**)&hbuf, g_h);
    cudaGetSymbolAddress((void**)&wq,   g_wq);
    cudaGetSymbolAddress((void**)&wk,   g_wk);
    cudaGetSymbolAddress((void**)&wv,   g_wv);
    cudaGetSymbolAddress((void**)&w1,   g_w1);
    cudaGetSymbolAddress((void**)&w2,   g_w2);

    cudaFuncSetAttribute(gemm_tc<0>, cudaFuncAttributeMaxDynamicSharedMemorySize, GEMM_SMEM);
    cudaFuncSetAttribute(gemm_tc<1>, cudaFuncAttributeMaxDynamicSharedMemorySize, GEMM_SMEM);
    cudaFuncSetAttribute(gemm_tc<2>, cudaFuncAttributeMaxDynamicSharedMemorySize, GEMM_SMEM);

    const int Mq = BATCH * NTOK;    // 40960
    const int Mkv = BATCH * KVTOK;  // 10240
    const int NDD = DMODEL * DMODEL;
    const int NFD = FFDIM * DMODEL;

    // weight pre-round to bf16 (runs every call for determinism)
    cvt_kernel<<<(NDD + 255) / 256, 256>>>(pq_w, wq, NDD);
    cvt_kernel<<<(NDD + 255) / 256, 256>>>(pk_w, wk, NDD);
    cvt_kernel<<<(NDD + 255) / 256, 256>>>(pv_w, wv, NDD);
    cvt_kernel<<<(NFD + 255) / 256, 256>>>(ff1_w, w1, NFD);
    cvt_kernel<<<(NFD + 255) / 256, 256>>>(ff2_w, w2, NFD);

    ln_kernel<float><<<Mq, 128>>>(x, ln1_g, ln1_b, xn);
    convq_kernel<<<dim3(NTOK, BATCH), DMODEL>>>(xn, dwq_w, dwq_b, bnq_g, bnq_b, cq);
    convkv_kernel<<<dim3(KVTOK, BATCH), DMODEL>>>(xn, dwk_w, dwk_b, bnk_g, bnk_b,
                                                  dwv_w, dwv_b, bnv_g, bnv_b, ck, cv);
    gemm_tc<0><<<dim3(DMODEL / BN, Mq / BM), 256, GEMM_SMEM>>>(cq, wq, pq_b, nullptr, q, Mq, DMODEL, DMODEL);
    gemm_tc<0><<<dim3(DMODEL / BN, Mkv / BM), 256, GEMM_SMEM>>>(ck, wk, pk_b, nullptr, k, Mkv, DMODEL, DMODEL);
    gemm_tc<0><<<dim3(DMODEL / BN, Mkv / BM), 256, GEMM_SMEM>>>(cv, wv, pv_b, nullptr, v, Mkv, DMODEL, DMODEL);
    attn_mma<<<dim3(NS_TOK / 64, NHEAD, BATCH), 128>>>(q, k, v, x, x1, 0, 0, KVTOK);
    attn_mma<<<dim3(NT_TOK / 64, NHEAD, BATCH), 128>>>(q, k, v, x, x1, NS_TOK, KV_S, KV_T);
    ln_kernel<__nv_bfloat16><<<Mq, 128>>>(x1, ln2_g, ln2_b, l2);
    gemm_tc<1><<<dim3(FFDIM / BN, Mq / BM), 256, GEMM_SMEM>>>(l2, w1, ff1_b, nullptr, hbuf, Mq, FFDIM, DMODEL);
    gemm_tc<2><<<dim3(DMODEL / BN, Mq / BM), 256, GEMM_SMEM>>>(hbuf, w2, ff2_b, x1, out, Mq, DMODEL, FFDIM);
}